// round 14
// baseline (speedup 1.0000x reference)
#include <cuda_runtime.h>
#include <cuda_bf16.h>
#include <stdint.h>
#include <math.h>

typedef unsigned long long ull;

// Problem constants
#define Bc 64
#define Tc 512
#define Ic 2048
#define Hc 256
#define Gc 768   // 3*H
#define Mr ((size_t)Bc * Tc)   // 32768 rows

// ---------------- device scratch (no allocations allowed) ----------------
__device__ float g_xg[Mr * Gc];     // xg buffer, reused per layer
__device__ float g_y0[Mr * Hc];
__device__ float g_y1[Mr * Hc];
__device__ float g_y2[Mr * Hc];
// pre-converted bf16 split operands (row-major, same layout as fp32 sources)
__device__ __nv_bfloat16 g_Ahi[Mr * Ic];
__device__ __nv_bfloat16 g_Alo[Mr * Ic];
__device__ __nv_bfloat16 g_Whi[(size_t)Gc * Ic];
__device__ __nv_bfloat16 g_Wlo[(size_t)Gc * Ic];

// ---------------- packed f32x2 helpers ----------------
__device__ __forceinline__ ull pack2(float x, float y) {
    ull r; asm("mov.b64 %0, {%1, %2};" : "=l"(r) : "f"(x), "f"(y)); return r;
}
__device__ __forceinline__ void unpack2(ull v, float& x, float& y) {
    asm("mov.b64 {%0, %1}, %2;" : "=f"(x), "=f"(y) : "l"(v));
}
__device__ __forceinline__ ull fma2(ull a, ull b, ull c) {
    ull d; asm("fma.rn.f32x2 %0, %1, %2, %3;" : "=l"(d) : "l"(a), "l"(b), "l"(c)); return d;
}
__device__ __forceinline__ ull add2(ull a, ull b) {
    ull d; asm("add.rn.f32x2 %0, %1, %2;" : "=l"(d) : "l"(a), "l"(b)); return d;
}
__device__ __forceinline__ float sigmoidf_(float x) {
    return __fdividef(1.0f, 1.0f + __expf(-x));
}
__device__ __forceinline__ float tanhf_(float x) {
    float a = fabsf(x);
    float e = __expf(-2.0f * a);
    float r = __fdividef(1.0f - e, 1.0f + e);
    return copysignf(r, x);
}
__device__ __forceinline__ unsigned smem_u32(const void* p) {
    return (unsigned)__cvta_generic_to_shared(p);
}

// ---------------- mma.sync / cp.async helpers ----------------
__device__ __forceinline__ void ldsm_x4(uint32_t& r0, uint32_t& r1, uint32_t& r2, uint32_t& r3,
                                        uint32_t addr) {
    asm volatile("ldmatrix.sync.aligned.m8n8.x4.shared.b16 {%0,%1,%2,%3}, [%4];"
                 : "=r"(r0), "=r"(r1), "=r"(r2), "=r"(r3) : "r"(addr));
}
__device__ __forceinline__ void mma_bf16(float& d0, float& d1, float& d2, float& d3,
                                         uint32_t a0, uint32_t a1, uint32_t a2, uint32_t a3,
                                         uint32_t b0, uint32_t b1) {
    asm volatile(
        "mma.sync.aligned.m16n8k16.row.col.f32.bf16.bf16.f32 "
        "{%0,%1,%2,%3},{%4,%5,%6,%7},{%8,%9},{%0,%1,%2,%3};"
        : "+f"(d0), "+f"(d1), "+f"(d2), "+f"(d3)
        : "r"(a0), "r"(a1), "r"(a2), "r"(a3), "r"(b0), "r"(b1));
}
__device__ __forceinline__ void cp16(uint32_t dst, const void* src) {
    asm volatile("cp.async.cg.shared.global [%0], [%1], 16;" :: "r"(dst), "l"(src));
}

// ---------------- cluster / mbarrier helpers ----------------
__device__ __forceinline__ void cluster_sync_() {
    asm volatile("barrier.cluster.arrive.aligned;" ::: "memory");
    asm volatile("barrier.cluster.wait.aligned;" ::: "memory");
}
__device__ __forceinline__ void mbar_init(uint32_t addr, uint32_t count) {
    asm volatile("mbarrier.init.shared.b64 [%0], %1;" :: "r"(addr), "r"(count) : "memory");
}
__device__ __forceinline__ void mbar_arrive_peer(uint32_t laddr, uint32_t rank2) {
    uint32_t raddr;
    asm("mapa.shared::cluster.u32 %0, %1, %2;" : "=r"(raddr) : "r"(laddr), "r"(rank2));
    asm volatile("mbarrier.arrive.release.cluster.shared::cluster.b64 _, [%0];"
                 :: "r"(raddr) : "memory");
}
__device__ __forceinline__ void mbar_wait_cluster(uint32_t addr, uint32_t parity) {
    asm volatile(
        "{\n\t.reg .pred P1;\n\t"
        "LAB_WAIT_%=:\n\t"
        "mbarrier.try_wait.parity.acquire.cluster.shared::cta.b64 P1, [%0], %1, 0x989680;\n\t"
        "@P1 bra.uni LAB_DONE_%=;\n\t"
        "bra.uni LAB_WAIT_%=;\n\t"
        "LAB_DONE_%=:\n\t}"
        :: "r"(addr), "r"(parity) : "memory");
}

// ---------------- convert: fp32 -> bf16 hi/lo (row-major, done ONCE) ----------------
__global__ __launch_bounds__(256) void convert_split(const float* __restrict__ src,
                                                     __nv_bfloat16* __restrict__ hi,
                                                     __nv_bfloat16* __restrict__ lo,
                                                     size_t total8) {
    size_t i = (size_t)blockIdx.x * 256 + threadIdx.x;
    if (i >= total8) return;
    const float4* s = (const float4*)src + i * 2;
    float4 v0 = s[0], v1 = s[1];
    float f[8] = {v0.x, v0.y, v0.z, v0.w, v1.x, v1.y, v1.z, v1.w};
    union { __nv_bfloat16 b[8]; uint4 u; } H, L;
#pragma unroll
    for (int j = 0; j < 8; j++) {
        H.b[j] = __float2bfloat16(f[j]);
        L.b[j] = __float2bfloat16(f[j] - __bfloat162float(H.b[j]));
    }
    ((uint4*)hi)[i] = H.u;
    ((uint4*)lo)[i] = L.u;
}

// ---------------- HMMA GEMM: g_xg[m,n] = A[m,:] . W[n,:] + bias[n] ----------------
#define LDAp 40
#define TILE_E (128 * LDAp)
#define STAGE_E (4 * TILE_E)
#define GEMM_SMEM (2 * STAGE_E * 2)

__global__ __launch_bounds__(256, 2)
void gemm_tc(const __nv_bfloat16* __restrict__ Ahi, const __nv_bfloat16* __restrict__ Alo,
             const __nv_bfloat16* __restrict__ Whi, const __nv_bfloat16* __restrict__ Wlo,
             const float* __restrict__ bias, int K) {
    extern __shared__ __nv_bfloat16 sm[];
    const uint32_t sbase = smem_u32(sm);
    const int tid = threadIdx.x, lane = tid & 31, wid = tid >> 5;
    const int wm = wid & 3, wn = wid >> 2;
    const int m0 = blockIdx.y * 128, n0 = blockIdx.x * 128;
    const int nkb = K >> 5;

    const int r0 = tid >> 2, r1 = 64 + r0, q = tid & 3;
    const uint32_t e0 = (uint32_t)(r0 * LDAp + q * 8) * 2;
    const uint32_t e1 = (uint32_t)(r1 * LDAp + q * 8) * 2;

    const __nv_bfloat16* a0p = Ahi + (size_t)(m0 + r0) * K + q * 8;
    const __nv_bfloat16* a1p = Ahi + (size_t)(m0 + r1) * K + q * 8;
    const __nv_bfloat16* l0p = Alo + (size_t)(m0 + r0) * K + q * 8;
    const __nv_bfloat16* l1p = Alo + (size_t)(m0 + r1) * K + q * 8;
    const __nv_bfloat16* w0p = Whi + (size_t)(n0 + r0) * K + q * 8;
    const __nv_bfloat16* w1p = Whi + (size_t)(n0 + r1) * K + q * 8;
    const __nv_bfloat16* v0p = Wlo + (size_t)(n0 + r0) * K + q * 8;
    const __nv_bfloat16* v1p = Wlo + (size_t)(n0 + r1) * K + q * 8;

    const int lrow = lane & 15, lcol = (lane >> 4) * 8;
    const uint32_t offA = ((wm * 32 + lrow) * LDAp + lcol) * 2;
    const uint32_t offB = ((wn * 64 + lrow) * LDAp + lcol) * 2;

    float acc[2][8][4];
#pragma unroll
    for (int i = 0; i < 2; i++)
#pragma unroll
        for (int j = 0; j < 8; j++)
#pragma unroll
            for (int qq = 0; qq < 4; qq++) acc[i][j][qq] = 0.0f;

    auto issue = [&](int kb) {
        const uint32_t st = sbase + (uint32_t)(kb & 1) * STAGE_E * 2;
        const int kc = kb * 32;
        cp16(st + e0, a0p + kc);
        cp16(st + e1, a1p + kc);
        cp16(st + TILE_E * 2 + e0, l0p + kc);
        cp16(st + TILE_E * 2 + e1, l1p + kc);
        cp16(st + 2 * TILE_E * 2 + e0, w0p + kc);
        cp16(st + 2 * TILE_E * 2 + e1, w1p + kc);
        cp16(st + 3 * TILE_E * 2 + e0, v0p + kc);
        cp16(st + 3 * TILE_E * 2 + e1, v1p + kc);
        asm volatile("cp.async.commit_group;");
    };

    issue(0);

    for (int kb = 0; kb < nkb; kb++) {
        if (kb + 1 < nkb) {
            issue(kb + 1);
            asm volatile("cp.async.wait_group 1;");
        } else {
            asm volatile("cp.async.wait_group 0;");
        }
        __syncthreads();

        const int p = kb & 1;
        const uint32_t bAhi = sbase + (uint32_t)p * STAGE_E * 2 + offA;
        const uint32_t bAlo = bAhi + TILE_E * 2;
        const uint32_t bWhi = sbase + (uint32_t)p * STAGE_E * 2 + 2 * TILE_E * 2 + offB;
        const uint32_t bWlo = bWhi + TILE_E * 2;
#pragma unroll
        for (int ks = 0; ks < 2; ks++) {
            const uint32_t ko = ks * 32;
            uint32_t ah[2][4], al[2][4];
#pragma unroll
            for (int ma = 0; ma < 2; ma++) {
                ldsm_x4(ah[ma][0], ah[ma][1], ah[ma][2], ah[ma][3],
                        bAhi + ko + ma * 16 * LDAp * 2);
                ldsm_x4(al[ma][0], al[ma][1], al[ma][2], al[ma][3],
                        bAlo + ko + ma * 16 * LDAp * 2);
            }
            uint32_t wh[4][4], wl[4][4];
#pragma unroll
            for (int pa = 0; pa < 4; pa++) {
                ldsm_x4(wh[pa][0], wh[pa][1], wh[pa][2], wh[pa][3],
                        bWhi + ko + pa * 16 * LDAp * 2);
                ldsm_x4(wl[pa][0], wl[pa][1], wl[pa][2], wl[pa][3],
                        bWlo + ko + pa * 16 * LDAp * 2);
            }
#pragma unroll
            for (int ma = 0; ma < 2; ma++) {
#pragma unroll
                for (int na = 0; na < 8; na++) {
                    const int pa = na >> 1, hf = na & 1;
                    float* d = acc[ma][na];
                    mma_bf16(d[0], d[1], d[2], d[3],
                             ah[ma][0], ah[ma][1], ah[ma][2], ah[ma][3],
                             wh[pa][hf], wh[pa][hf + 2]);
                    mma_bf16(d[0], d[1], d[2], d[3],
                             ah[ma][0], ah[ma][1], ah[ma][2], ah[ma][3],
                             wl[pa][hf], wl[pa][hf + 2]);
                    mma_bf16(d[0], d[1], d[2], d[3],
                             al[ma][0], al[ma][1], al[ma][2], al[ma][3],
                             wh[pa][hf], wh[pa][hf + 2]);
                }
            }
        }
        __syncthreads();
    }

#pragma unroll
    for (int ma = 0; ma < 2; ma++) {
#pragma unroll
        for (int na = 0; na < 8; na++) {
            int row = m0 + wm * 32 + ma * 16 + (lane >> 2);
            int col = n0 + wn * 64 + na * 8 + (lane & 3) * 2;
            float b0 = __ldg(bias + col), b1 = __ldg(bias + col + 1);
            float* d = acc[ma][na];
            *(float2*)&g_xg[(size_t)row * Gc + col] = make_float2(d[0] + b0, d[1] + b1);
            *(float2*)&g_xg[(size_t)(row + 8) * Gc + col] = make_float2(d[2] + b0, d[3] + b1);
        }
    }
}

// ---------------- cluster-based persistent recurrent scan ----------------
// Per-step sync via point-to-point mbarriers (producer/consumer), not barrier.cluster.
#define SCAN_THREADS 384

__global__ __launch_bounds__(SCAN_THREADS, 1) __cluster_dims__(4, 1, 1)
void scan_kernel(const float* __restrict__ w_hh,
                 const float* __restrict__ b_hh,
                 int layer) {
    __shared__ __align__(16) ull hdup[2][2][Hc];   // [buf][batch][k] = (h,h)
    __shared__ __align__(16) ull part[8][96];      // [kq*2+b][cp] packed col-pair partials
    __shared__ __align__(16) float biasf[192];     // b_hh slice (gate-major)
    __shared__ __align__(8)  ull mbar[2];          // phase barriers, one per h buffer

    const float* xg = g_xg;
    float* yout = (layer == 0) ? g_y0 : (layer == 1 ? g_y1 : g_y2);

    const int tid  = threadIdx.x;
    const int rank = blockIdx.x;
    const int B0   = blockIdx.y * 2;

    const int cp = tid % 96;
    const int kq = tid / 96;
    const int kbase = kq * 64;
    const int c0 = 2 * cp;
    const int s  = c0 >> 6;
    const int jl = c0 & 63;
    const int grow = s * 256 + 64 * rank + jl;

    if (tid < 192) {
        int ss = tid >> 6, jj = tid & 63;
        biasf[tid] = b_hh[ss * 256 + 64 * rank + jj];
    }
    for (int idx = tid; idx < 2 * Hc; idx += SCAN_THREADS) {
        hdup[0][idx >> 8][idx & 255] = 0ULL;
    }
    if (tid == 0) {
        mbar_init(smem_u32(&mbar[0]), 384);   // 3 peers x 128 threads
        mbar_init(smem_u32(&mbar[1]), 384);
    }

    ull wreg[64];
    {
        const float* w0p = w_hh + (size_t)grow * Hc + kbase;
        const float* w1p = w0p + Hc;
#pragma unroll
        for (int i = 0; i < 64; i++) wreg[i] = pack2(__ldg(w0p + i), __ldg(w1p + i));
    }
    __syncthreads();
    cluster_sync_();   // publish mbarrier inits + zeroed h before any peer arrivals

    const unsigned hbase_u32[2] = { smem_u32(&hdup[0][0][0]), smem_u32(&hdup[1][0][0]) };
    const unsigned mbar_u32[2]  = { smem_u32(&mbar[0]), smem_u32(&mbar[1]) };
    const float* partf = (const float*)part;

    // pointwise threads are warps 8..11 (hi-wid arbiter priority on the tail phase)
    const bool pw = (tid >= 256);
    const int pt = tid - 256;                       // 0..127 for pointwise threads
    const int pb = pw ? (pt >> 6) : 0;
    const int pj = pt & 63;
    const float* xbase = xg + ((size_t)(B0 + pb) * Tc) * Gc + 64 * rank + pj;
    float xr = 0.f, xz = 0.f, xn = 0.f;
    if (pw) {
        const float* xp = xbase;  // t = 0
        xr = __ldg(xp); xz = __ldg(xp + 256); xn = __ldg(xp + 512);
    }

    int ph0 = 0, ph1 = 0;

    for (int t = 0; t < Tc; t++) {
        const int p = t & 1;

        // wait for peers' h slices for this step (arrivals from step t-1)
        if (t > 0) {
            if (p) { mbar_wait_cluster(mbar_u32[1], ph1); ph1 ^= 1; }
            else   { mbar_wait_cluster(mbar_u32[0], ph0); ph0 ^= 1; }
        }

        {
            const ull* h0 = &hdup[p][0][kbase];
            const ull* h1 = &hdup[p][1][kbase];
            ull a0 = 0ULL, a1 = 0ULL, bb0 = 0ULL, bb1 = 0ULL;
#pragma unroll
            for (int i = 0; i < 64; i += 2) {
                ulonglong2 ha = *(const ulonglong2*)(h0 + i);
                ulonglong2 hb = *(const ulonglong2*)(h1 + i);
                a0  = fma2(ha.x, wreg[i],     a0);
                bb0 = fma2(hb.x, wreg[i],     bb0);
                a1  = fma2(ha.y, wreg[i + 1], a1);
                bb1 = fma2(hb.y, wreg[i + 1], bb1);
            }
            part[kq * 2 + 0][cp] = add2(a0, a1);
            part[kq * 2 + 1][cp] = add2(bb0, bb1);
        }
        __syncthreads();

        // prefetch xg(t+1) early — consumed next iteration
        float nxr = 0.f, nxz = 0.f, nxn = 0.f;
        if (pw && t + 1 < Tc) {
            const float* xp = xbase + (size_t)(t + 1) * Gc;
            nxr = __ldg(xp); nxz = __ldg(xp + 256); nxn = __ldg(xp + 512);
        }

        // merged reduce + pointwise + DSMEM broadcast + mbarrier arrive
        if (pw) {
            int b = pb, j = pj;
            int slot = 64 * rank + j;
            int cpr = (j >> 1), par = j & 1;
            float hr = 0.f, hz = 0.f, hn = 0.f;
#pragma unroll
            for (int k = 0; k < 4; k++) {
                int base = ((k * 2 + b) * 96) * 2;
                hr += partf[base + (cpr) * 2 + par];
                hz += partf[base + (32 + cpr) * 2 + par];
                hn += partf[base + (64 + cpr) * 2 + par];
            }
            hr += biasf[j]; hz += biasf[64 + j]; hn += biasf[128 + j];
            float hp, dummy;
            unpack2(hdup[p][b][slot], hp, dummy);
            float r = sigmoidf_(xr + hr);
            float z = sigmoidf_(xz + hz);
            float n = tanhf_(xn + r * hn);
            float hnew = fmaf(z, hp - n, n);
            ull hd = pack2(hnew, hnew);
            hdup[p ^ 1][b][slot] = hd;
            unsigned laddr = hbase_u32[p ^ 1] + (unsigned)((b * Hc + slot) * 8);
            unsigned lmb   = mbar_u32[p ^ 1];
#pragma unroll
            for (int pr = 1; pr < 4; pr++) {
                unsigned r2 = (rank + pr) & 3;
                unsigned raddr;
                asm("mapa.shared::cluster.u32 %0, %1, %2;" : "=r"(raddr) : "r"(laddr), "r"(r2));
                asm volatile("st.shared::cluster.b64 [%0], %1;" :: "r"(raddr), "l"(hd) : "memory");
            }
#pragma unroll
            for (int pr = 1; pr < 4; pr++) {
                mbar_arrive_peer(lmb, (rank + pr) & 3);
            }
            if (layer != 2 || t == Tc - 1)
                yout[((size_t)(B0 + b) * Tc + t) * Hc + slot] = hnew;
        }

        __syncthreads();   // local h visibility for next step's GEMM
        xr = nxr; xz = nxz; xn = nxn;
    }

    cluster_sync_();   // no CTA may exit while peers still write into its SMEM
}

// ---------------- FC head ----------------
__global__ __launch_bounds__(128) void fc_kernel(const float* __restrict__ fc1_w,
                                                 const float* __restrict__ fc1_b,
                                                 const float* __restrict__ fco_w,
                                                 const float* __restrict__ fco_b,
                                                 float* __restrict__ out) {
    int b = blockIdx.x;
    int f = threadIdx.x;
    const float* last = g_y2 + ((size_t)b * Tc + (Tc - 1)) * Hc;
    __shared__ float ls[256];
    for (int k = f; k < 256; k += 128) ls[k] = last[k];
    __syncthreads();
    float acc = fc1_b[f];
    const float* wr = fc1_w + (size_t)f * 256;
#pragma unroll 8
    for (int k = 0; k < 256; k++) acc = fmaf(ls[k], wr[k], acc);
    float z = fmaxf(acc, 0.0f);
    float v = z * fco_w[f];
#pragma unroll
    for (int o = 16; o > 0; o >>= 1) v += __shfl_xor_sync(0xffffffffu, v, o);
    __shared__ float ws[4];
    if ((f & 31) == 0) ws[f >> 5] = v;
    __syncthreads();
    if (f == 0) out[b] = ws[0] + ws[1] + ws[2] + ws[3] + fco_b[0];
}

// ---------------- launch ----------------
extern "C" void kernel_launch(void* const* d_in, const int* in_sizes, int n_in,
                              void* d_out, int out_size) {
    const float* x     = (const float*)d_in[0];
    const float* w_ih0 = (const float*)d_in[1];
    const float* w_hh0 = (const float*)d_in[2];
    const float* b_ih0 = (const float*)d_in[3];
    const float* b_hh0 = (const float*)d_in[4];
    const float* w_ih1 = (const float*)d_in[5];
    const float* w_hh1 = (const float*)d_in[6];
    const float* b_ih1 = (const float*)d_in[7];
    const float* b_hh1 = (const float*)d_in[8];
    const float* w_ih2 = (const float*)d_in[9];
    const float* w_hh2 = (const float*)d_in[10];
    const float* b_ih2 = (const float*)d_in[11];
    const float* b_hh2 = (const float*)d_in[12];
    const float* fc1_w = (const float*)d_in[13];
    const float* fc1_b = (const float*)d_in[14];
    const float* fco_w = (const float*)d_in[15];
    const float* fco_b = (const float*)d_in[16];
    float* out = (float*)d_out;

    cudaFuncSetAttribute(gemm_tc, cudaFuncAttributeMaxDynamicSharedMemorySize, GEMM_SMEM);

    __nv_bfloat16 *Ahi, *Alo, *Whi, *Wlo;
    cudaGetSymbolAddress((void**)&Ahi, g_Ahi);
    cudaGetSymbolAddress((void**)&Alo, g_Alo);
    cudaGetSymbolAddress((void**)&Whi, g_Whi);
    cudaGetSymbolAddress((void**)&Wlo, g_Wlo);
    float* y0p; cudaGetSymbolAddress((void**)&y0p, g_y0);
    float* y1p; cudaGetSymbolAddress((void**)&y1p, g_y1);

    dim3 ggrid(6, 256);      // N tiles x M tiles
    dim3 sgrid(4, 32);       // 32 clusters x 4 CTAs

    const size_t a8big = Mr * Ic / 8, w8big = (size_t)Gc * Ic / 8;
    const size_t a8sm  = Mr * Hc / 8, w8sm  = (size_t)Gc * Hc / 8;

    // layer 0
    convert_split<<<(unsigned)((a8big + 255) / 256), 256>>>(x, Ahi, Alo, a8big);
    convert_split<<<(unsigned)((w8big + 255) / 256), 256>>>(w_ih0, Whi, Wlo, w8big);
    gemm_tc<<<ggrid, 256, GEMM_SMEM>>>(Ahi, Alo, Whi, Wlo, b_ih0, Ic);
    scan_kernel<<<sgrid, SCAN_THREADS>>>(w_hh0, b_hh0, 0);
    // layer 1
    convert_split<<<(unsigned)((a8sm + 255) / 256), 256>>>(y0p, Ahi, Alo, a8sm);
    convert_split<<<(unsigned)((w8sm + 255) / 256), 256>>>(w_ih1, Whi, Wlo, w8sm);
    gemm_tc<<<ggrid, 256, GEMM_SMEM>>>(Ahi, Alo, Whi, Wlo, b_ih1, Hc);
    scan_kernel<<<sgrid, SCAN_THREADS>>>(w_hh1, b_hh1, 1);
    // layer 2
    convert_split<<<(unsigned)((a8sm + 255) / 256), 256>>>(y1p, Ahi, Alo, a8sm);
    convert_split<<<(unsigned)((w8sm + 255) / 256), 256>>>(w_ih2, Whi, Wlo, w8sm);
    gemm_tc<<<ggrid, 256, GEMM_SMEM>>>(Ahi, Alo, Whi, Wlo, b_ih2, Hc);
    scan_kernel<<<sgrid, SCAN_THREADS>>>(w_hh2, b_hh2, 2);
    // head
    fc_kernel<<<64, 128>>>(fc1_w, fc1_b, fco_w, fco_b, out);
}

// round 15
// speedup vs baseline: 1.3079x; 1.3079x over previous
#include <cuda_runtime.h>
#include <cuda_bf16.h>
#include <stdint.h>
#include <math.h>

typedef unsigned long long ull;

// Problem constants
#define Bc 64
#define Tc 512
#define Ic 2048
#define Hc 256
#define Gc 768   // 3*H
#define Mr ((size_t)Bc * Tc)   // 32768 rows

// ---------------- device scratch (no allocations allowed) ----------------
__device__ float g_xg[Mr * Gc];     // xg buffer, reused per layer
__device__ float g_y2[Mr * Hc];     // layer2 output (only last t actually used)
// pre-converted bf16 split operands (row-major, same layout as fp32 sources)
__device__ __nv_bfloat16 g_Ahi[Mr * Ic];
__device__ __nv_bfloat16 g_Alo[Mr * Ic];
__device__ __nv_bfloat16 g_Whi[(size_t)Gc * Ic];
__device__ __nv_bfloat16 g_Wlo[(size_t)Gc * Ic];

// ---------------- packed f32x2 helpers ----------------
__device__ __forceinline__ ull pack2(float x, float y) {
    ull r; asm("mov.b64 %0, {%1, %2};" : "=l"(r) : "f"(x), "f"(y)); return r;
}
__device__ __forceinline__ void unpack2(ull v, float& x, float& y) {
    asm("mov.b64 {%0, %1}, %2;" : "=f"(x), "=f"(y) : "l"(v));
}
__device__ __forceinline__ ull fma2(ull a, ull b, ull c) {
    ull d; asm("fma.rn.f32x2 %0, %1, %2, %3;" : "=l"(d) : "l"(a), "l"(b), "l"(c)); return d;
}
__device__ __forceinline__ ull add2(ull a, ull b) {
    ull d; asm("add.rn.f32x2 %0, %1, %2;" : "=l"(d) : "l"(a), "l"(b)); return d;
}
__device__ __forceinline__ float sigmoidf_(float x) {
    return __fdividef(1.0f, 1.0f + __expf(-x));
}
__device__ __forceinline__ float tanhf_(float x) {
    float a = fabsf(x);
    float e = __expf(-2.0f * a);
    float r = __fdividef(1.0f - e, 1.0f + e);
    return copysignf(r, x);
}
__device__ __forceinline__ unsigned smem_u32(const void* p) {
    return (unsigned)__cvta_generic_to_shared(p);
}

// ---------------- mma.sync / cp.async helpers ----------------
__device__ __forceinline__ void ldsm_x4(uint32_t& r0, uint32_t& r1, uint32_t& r2, uint32_t& r3,
                                        uint32_t addr) {
    asm volatile("ldmatrix.sync.aligned.m8n8.x4.shared.b16 {%0,%1,%2,%3}, [%4];"
                 : "=r"(r0), "=r"(r1), "=r"(r2), "=r"(r3) : "r"(addr));
}
__device__ __forceinline__ void mma_bf16(float& d0, float& d1, float& d2, float& d3,
                                         uint32_t a0, uint32_t a1, uint32_t a2, uint32_t a3,
                                         uint32_t b0, uint32_t b1) {
    asm volatile(
        "mma.sync.aligned.m16n8k16.row.col.f32.bf16.bf16.f32 "
        "{%0,%1,%2,%3},{%4,%5,%6,%7},{%8,%9},{%0,%1,%2,%3};"
        : "+f"(d0), "+f"(d1), "+f"(d2), "+f"(d3)
        : "r"(a0), "r"(a1), "r"(a2), "r"(a3), "r"(b0), "r"(b1));
}
__device__ __forceinline__ void cp16(uint32_t dst, const void* src) {
    asm volatile("cp.async.cg.shared.global [%0], [%1], 16;" :: "r"(dst), "l"(src));
}

// ---------------- cluster helpers ----------------
__device__ __forceinline__ void cluster_sync_() {
    asm volatile("barrier.cluster.arrive.aligned;" ::: "memory");
    asm volatile("barrier.cluster.wait.aligned;" ::: "memory");
}

// ---------------- convert: fp32 -> bf16 hi/lo (row-major, done ONCE) ----------------
__global__ __launch_bounds__(256) void convert_split(const float* __restrict__ src,
                                                     __nv_bfloat16* __restrict__ hi,
                                                     __nv_bfloat16* __restrict__ lo,
                                                     size_t total8) {
    size_t i = (size_t)blockIdx.x * 256 + threadIdx.x;
    if (i >= total8) return;
    const float4* s = (const float4*)src + i * 2;
    float4 v0 = s[0], v1 = s[1];
    float f[8] = {v0.x, v0.y, v0.z, v0.w, v1.x, v1.y, v1.z, v1.w};
    union { __nv_bfloat16 b[8]; uint4 u; } H, L;
#pragma unroll
    for (int j = 0; j < 8; j++) {
        H.b[j] = __float2bfloat16(f[j]);
        L.b[j] = __float2bfloat16(f[j] - __bfloat162float(H.b[j]));
    }
    ((uint4*)hi)[i] = H.u;
    ((uint4*)lo)[i] = L.u;
}

// ---------------- HMMA GEMM: g_xg[m,n] = A[m,:] . W[n,:] + bias[n] ----------------
// BM=BN=128, BK=32, 256 threads (8 warps, warp tile 32x64), 2 CTAs/SM.
// Split-bf16 3-term: acc += Ahi*Whi + Ahi*Wlo + Alo*Whi (fp32 accumulate).
// cp.async double buffer with ONE __syncthreads per chunk:
//   wait_group 0 -> sync -> issue(kb+1) -> compute(kb)
#define LDAp 40
#define TILE_E (128 * LDAp)
#define STAGE_E (4 * TILE_E)
#define GEMM_SMEM (2 * STAGE_E * 2)

__global__ __launch_bounds__(256, 2)
void gemm_tc(const __nv_bfloat16* __restrict__ Ahi, const __nv_bfloat16* __restrict__ Alo,
             const __nv_bfloat16* __restrict__ Whi, const __nv_bfloat16* __restrict__ Wlo,
             const float* __restrict__ bias, int K) {
    extern __shared__ __nv_bfloat16 sm[];
    const uint32_t sbase = smem_u32(sm);
    const int tid = threadIdx.x, lane = tid & 31, wid = tid >> 5;
    const int wm = wid & 3, wn = wid >> 2;
    const int m0 = blockIdx.y * 128, n0 = blockIdx.x * 128;
    const int nkb = K >> 5;

    const int r0 = tid >> 2, r1 = 64 + r0, q = tid & 3;
    const uint32_t e0 = (uint32_t)(r0 * LDAp + q * 8) * 2;
    const uint32_t e1 = (uint32_t)(r1 * LDAp + q * 8) * 2;

    const __nv_bfloat16* a0p = Ahi + (size_t)(m0 + r0) * K + q * 8;
    const __nv_bfloat16* a1p = Ahi + (size_t)(m0 + r1) * K + q * 8;
    const __nv_bfloat16* l0p = Alo + (size_t)(m0 + r0) * K + q * 8;
    const __nv_bfloat16* l1p = Alo + (size_t)(m0 + r1) * K + q * 8;
    const __nv_bfloat16* w0p = Whi + (size_t)(n0 + r0) * K + q * 8;
    const __nv_bfloat16* w1p = Whi + (size_t)(n0 + r1) * K + q * 8;
    const __nv_bfloat16* v0p = Wlo + (size_t)(n0 + r0) * K + q * 8;
    const __nv_bfloat16* v1p = Wlo + (size_t)(n0 + r1) * K + q * 8;

    const int lrow = lane & 15, lcol = (lane >> 4) * 8;
    const uint32_t offA = ((wm * 32 + lrow) * LDAp + lcol) * 2;
    const uint32_t offB = ((wn * 64 + lrow) * LDAp + lcol) * 2;

    float acc[2][8][4];
#pragma unroll
    for (int i = 0; i < 2; i++)
#pragma unroll
        for (int j = 0; j < 8; j++)
#pragma unroll
            for (int qq = 0; qq < 4; qq++) acc[i][j][qq] = 0.0f;

    auto issue = [&](int kb) {
        const uint32_t st = sbase + (uint32_t)(kb & 1) * STAGE_E * 2;
        const int kc = kb * 32;
        cp16(st + e0, a0p + kc);
        cp16(st + e1, a1p + kc);
        cp16(st + TILE_E * 2 + e0, l0p + kc);
        cp16(st + TILE_E * 2 + e1, l1p + kc);
        cp16(st + 2 * TILE_E * 2 + e0, w0p + kc);
        cp16(st + 2 * TILE_E * 2 + e1, w1p + kc);
        cp16(st + 3 * TILE_E * 2 + e0, v0p + kc);
        cp16(st + 3 * TILE_E * 2 + e1, v1p + kc);
        asm volatile("cp.async.commit_group;");
    };

    issue(0);

    for (int kb = 0; kb < nkb; kb++) {
        asm volatile("cp.async.wait_group 0;");
        __syncthreads();
        if (kb + 1 < nkb) issue(kb + 1);   // fills the other buffer; overlaps compute below

        const int p = kb & 1;
        const uint32_t bAhi = sbase + (uint32_t)p * STAGE_E * 2 + offA;
        const uint32_t bAlo = bAhi + TILE_E * 2;
        const uint32_t bWhi = sbase + (uint32_t)p * STAGE_E * 2 + 2 * TILE_E * 2 + offB;
        const uint32_t bWlo = bWhi + TILE_E * 2;
#pragma unroll
        for (int ks = 0; ks < 2; ks++) {
            const uint32_t ko = ks * 32;
            uint32_t ah[2][4], al[2][4];
#pragma unroll
            for (int ma = 0; ma < 2; ma++) {
                ldsm_x4(ah[ma][0], ah[ma][1], ah[ma][2], ah[ma][3],
                        bAhi + ko + ma * 16 * LDAp * 2);
                ldsm_x4(al[ma][0], al[ma][1], al[ma][2], al[ma][3],
                        bAlo + ko + ma * 16 * LDAp * 2);
            }
            uint32_t wh[4][4], wl[4][4];
#pragma unroll
            for (int pa = 0; pa < 4; pa++) {
                ldsm_x4(wh[pa][0], wh[pa][1], wh[pa][2], wh[pa][3],
                        bWhi + ko + pa * 16 * LDAp * 2);
                ldsm_x4(wl[pa][0], wl[pa][1], wl[pa][2], wl[pa][3],
                        bWlo + ko + pa * 16 * LDAp * 2);
            }
#pragma unroll
            for (int ma = 0; ma < 2; ma++) {
#pragma unroll
                for (int na = 0; na < 8; na++) {
                    const int pa = na >> 1, hf = na & 1;
                    float* d = acc[ma][na];
                    mma_bf16(d[0], d[1], d[2], d[3],
                             ah[ma][0], ah[ma][1], ah[ma][2], ah[ma][3],
                             wh[pa][hf], wh[pa][hf + 2]);
                    mma_bf16(d[0], d[1], d[2], d[3],
                             ah[ma][0], ah[ma][1], ah[ma][2], ah[ma][3],
                             wl[pa][hf], wl[pa][hf + 2]);
                    mma_bf16(d[0], d[1], d[2], d[3],
                             al[ma][0], al[ma][1], al[ma][2], al[ma][3],
                             wh[pa][hf], wh[pa][hf + 2]);
                }
            }
        }
    }

#pragma unroll
    for (int ma = 0; ma < 2; ma++) {
#pragma unroll
        for (int na = 0; na < 8; na++) {
            int row = m0 + wm * 32 + ma * 16 + (lane >> 2);
            int col = n0 + wn * 64 + na * 8 + (lane & 3) * 2;
            float b0 = __ldg(bias + col), b1 = __ldg(bias + col + 1);
            float* d = acc[ma][na];
            *(float2*)&g_xg[(size_t)row * Gc + col] = make_float2(d[0] + b0, d[1] + b1);
            *(float2*)&g_xg[(size_t)(row + 8) * Gc + col] = make_float2(d[2] + b0, d[3] + b1);
        }
    }
}

// ---------------- cluster-based persistent recurrent scan (R11 design) ----------------
// Per-step sync: barrier.cluster. Pointwise threads also emit bf16 hi/lo split of h
// (feeds the next layer's GEMM directly; no separate convert pass for layers 1/2).
#define SCAN_THREADS 384

__global__ __launch_bounds__(SCAN_THREADS, 1) __cluster_dims__(4, 1, 1)
void scan_kernel(const float* __restrict__ w_hh,
                 const float* __restrict__ b_hh,
                 int layer) {
    __shared__ __align__(16) ull hdup[2][2][Hc];   // [buf][batch][k] = (h,h)
    __shared__ __align__(16) ull part[8][96];      // [kq*2+b][cp] packed col-pair partials
    __shared__ __align__(16) float biasf[192];     // b_hh slice (gate-major)

    const float* xg = g_xg;

    const int tid  = threadIdx.x;
    const int rank = blockIdx.x;
    const int B0   = blockIdx.y * 2;

    const int cp = tid % 96;
    const int kq = tid / 96;
    const int kbase = kq * 64;
    const int c0 = 2 * cp;
    const int s  = c0 >> 6;
    const int jl = c0 & 63;
    const int grow = s * 256 + 64 * rank + jl;

    if (tid < 192) {
        int ss = tid >> 6, jj = tid & 63;
        biasf[tid] = b_hh[ss * 256 + 64 * rank + jj];
    }
    for (int idx = tid; idx < 2 * Hc; idx += SCAN_THREADS) {
        hdup[0][idx >> 8][idx & 255] = 0ULL;
    }

    ull wreg[64];
    {
        const float* w0p = w_hh + (size_t)grow * Hc + kbase;
        const float* w1p = w0p + Hc;
#pragma unroll
        for (int i = 0; i < 64; i++) wreg[i] = pack2(__ldg(w0p + i), __ldg(w1p + i));
    }
    __syncthreads();

    const unsigned hbase_u32[2] = { smem_u32(&hdup[0][0][0]), smem_u32(&hdup[1][0][0]) };
    const float* partf = (const float*)part;

    // software-pipelined xg for step 0 (pointwise threads = tid < 128)
    const int pb = (tid < 128) ? (tid >> 6) : 0;
    const int pj = tid & 63;
    const float* xbase = xg + ((size_t)(B0 + pb) * Tc) * Gc + 64 * rank + pj;
    float xr = 0.f, xz = 0.f, xn = 0.f;
    if (tid < 128) {
        const float* xp = xbase;  // t = 0
        xr = __ldg(xp); xz = __ldg(xp + 256); xn = __ldg(xp + 512);
    }

    for (int t = 0; t < Tc; t++) {
        const int p = t & 1;

        {
            const ull* h0 = &hdup[p][0][kbase];
            const ull* h1 = &hdup[p][1][kbase];
            ull a0 = 0ULL, a1 = 0ULL, bb0 = 0ULL, bb1 = 0ULL;
#pragma unroll
            for (int i = 0; i < 64; i += 2) {
                ulonglong2 ha = *(const ulonglong2*)(h0 + i);
                ulonglong2 hb = *(const ulonglong2*)(h1 + i);
                a0  = fma2(ha.x, wreg[i],     a0);
                bb0 = fma2(hb.x, wreg[i],     bb0);
                a1  = fma2(ha.y, wreg[i + 1], a1);
                bb1 = fma2(hb.y, wreg[i + 1], bb1);
            }
            part[kq * 2 + 0][cp] = add2(a0, a1);
            part[kq * 2 + 1][cp] = add2(bb0, bb1);
        }
        __syncthreads();

        // prefetch xg(t+1) early — consumed next iteration
        float nxr = 0.f, nxz = 0.f, nxn = 0.f;
        if (tid < 128 && t + 1 < Tc) {
            const float* xp = xbase + (size_t)(t + 1) * Gc;
            nxr = __ldg(xp); nxz = __ldg(xp + 256); nxn = __ldg(xp + 512);
        }

        // merged reduce + pointwise
        if (tid < 128) {
            int b = pb, j = pj;
            int slot = 64 * rank + j;
            int cpr = (j >> 1), par = j & 1;
            float hr = 0.f, hz = 0.f, hn = 0.f;
#pragma unroll
            for (int k = 0; k < 4; k++) {
                int base = ((k * 2 + b) * 96) * 2;
                hr += partf[base + (cpr) * 2 + par];
                hz += partf[base + (32 + cpr) * 2 + par];
                hn += partf[base + (64 + cpr) * 2 + par];
            }
            hr += biasf[j]; hz += biasf[64 + j]; hn += biasf[128 + j];
            float hp, dummy;
            unpack2(hdup[p][b][slot], hp, dummy);
            float r = sigmoidf_(xr + hr);
            float z = sigmoidf_(xz + hz);
            float n = tanhf_(xn + r * hn);
            float hnew = fmaf(z, hp - n, n);
            ull hd = pack2(hnew, hnew);
            hdup[p ^ 1][b][slot] = hd;
            unsigned laddr = hbase_u32[p ^ 1] + (unsigned)((b * Hc + slot) * 8);
#pragma unroll
            for (int pr = 1; pr < 4; pr++) {
                unsigned r2 = (rank + pr) & 3;
                unsigned raddr;
                asm("mapa.shared::cluster.u32 %0, %1, %2;" : "=r"(raddr) : "r"(laddr), "r"(r2));
                asm volatile("st.shared::cluster.b64 [%0], %1;" :: "r"(raddr), "l"(hd) : "memory");
            }
            // emit outputs
            size_t orow = (size_t)(B0 + b) * Tc + t;
            if (layer != 2) {
                // next layer consumes bf16 split directly
                __nv_bfloat16 hh = __float2bfloat16(hnew);
                __nv_bfloat16 hl = __float2bfloat16(hnew - __bfloat162float(hh));
                g_Ahi[orow * Hc + slot] = hh;
                g_Alo[orow * Hc + slot] = hl;
            } else if (t == Tc - 1) {
                g_y2[orow * Hc + slot] = hnew;
            }
        }

        cluster_sync_();
        xr = nxr; xz = nxz; xn = nxn;
    }
}

// ---------------- FC head ----------------
__global__ __launch_bounds__(128) void fc_kernel(const float* __restrict__ fc1_w,
                                                 const float* __restrict__ fc1_b,
                                                 const float* __restrict__ fco_w,
                                                 const float* __restrict__ fco_b,
                                                 float* __restrict__ out) {
    int b = blockIdx.x;
    int f = threadIdx.x;
    const float* last = g_y2 + ((size_t)b * Tc + (Tc - 1)) * Hc;
    __shared__ float ls[256];
    for (int k = f; k < 256; k += 128) ls[k] = last[k];
    __syncthreads();
    float acc = fc1_b[f];
    const float* wr = fc1_w + (size_t)f * 256;
#pragma unroll 8
    for (int k = 0; k < 256; k++) acc = fmaf(ls[k], wr[k], acc);
    float z = fmaxf(acc, 0.0f);
    float v = z * fco_w[f];
#pragma unroll
    for (int o = 16; o > 0; o >>= 1) v += __shfl_xor_sync(0xffffffffu, v, o);
    __shared__ float ws[4];
    if ((f & 31) == 0) ws[f >> 5] = v;
    __syncthreads();
    if (f == 0) out[b] = ws[0] + ws[1] + ws[2] + ws[3] + fco_b[0];
}

// ---------------- launch ----------------
extern "C" void kernel_launch(void* const* d_in, const int* in_sizes, int n_in,
                              void* d_out, int out_size) {
    const float* x     = (const float*)d_in[0];
    const float* w_ih0 = (const float*)d_in[1];
    const float* w_hh0 = (const float*)d_in[2];
    const float* b_ih0 = (const float*)d_in[3];
    const float* b_hh0 = (const float*)d_in[4];
    const float* w_ih1 = (const float*)d_in[5];
    const float* w_hh1 = (const float*)d_in[6];
    const float* b_ih1 = (const float*)d_in[7];
    const float* b_hh1 = (const float*)d_in[8];
    const float* w_ih2 = (const float*)d_in[9];
    const float* w_hh2 = (const float*)d_in[10];
    const float* b_ih2 = (const float*)d_in[11];
    const float* b_hh2 = (const float*)d_in[12];
    const float* fc1_w = (const float*)d_in[13];
    const float* fc1_b = (const float*)d_in[14];
    const float* fco_w = (const float*)d_in[15];
    const float* fco_b = (const float*)d_in[16];
    float* out = (float*)d_out;

    cudaFuncSetAttribute(gemm_tc, cudaFuncAttributeMaxDynamicSharedMemorySize, GEMM_SMEM);

    __nv_bfloat16 *Ahi, *Alo, *Whi, *Wlo;
    cudaGetSymbolAddress((void**)&Ahi, g_Ahi);
    cudaGetSymbolAddress((void**)&Alo, g_Alo);
    cudaGetSymbolAddress((void**)&Whi, g_Whi);
    cudaGetSymbolAddress((void**)&Wlo, g_Wlo);

    dim3 ggrid(6, 256);      // N tiles x M tiles
    dim3 sgrid(4, 32);       // 32 clusters x 4 CTAs

    const size_t a8big = Mr * Ic / 8, w8big = (size_t)Gc * Ic / 8;
    const size_t w8sm  = (size_t)Gc * Hc / 8;

    // layer 0
    convert_split<<<(unsigned)((a8big + 255) / 256), 256>>>(x, Ahi, Alo, a8big);
    convert_split<<<(unsigned)((w8big + 255) / 256), 256>>>(w_ih0, Whi, Wlo, w8big);
    gemm_tc<<<ggrid, 256, GEMM_SMEM>>>(Ahi, Alo, Whi, Wlo, b_ih0, Ic);
    scan_kernel<<<sgrid, SCAN_THREADS>>>(w_hh0, b_hh0, 0);   // writes bf16 split y0 -> g_Ahi/g_Alo
    // layer 1
    convert_split<<<(unsigned)((w8sm + 255) / 256), 256>>>(w_ih1, Whi, Wlo, w8sm);
    gemm_tc<<<ggrid, 256, GEMM_SMEM>>>(Ahi, Alo, Whi, Wlo, b_ih1, Hc);
    scan_kernel<<<sgrid, SCAN_THREADS>>>(w_hh1, b_hh1, 1);   // writes bf16 split y1 -> g_Ahi/g_Alo
    // layer 2
    convert_split<<<(unsigned)((w8sm + 255) / 256), 256>>>(w_ih2, Whi, Wlo, w8sm);
    gemm_tc<<<ggrid, 256, GEMM_SMEM>>>(Ahi, Alo, Whi, Wlo, b_ih2, Hc);
    scan_kernel<<<sgrid, SCAN_THREADS>>>(w_hh2, b_hh2, 2);   // writes fp32 last h -> g_y2
    // head
    fc_kernel<<<64, 128>>>(fc1_w, fc1_b, fco_w, fco_b, out);
}